// round 14
// baseline (speedup 1.0000x reference)
#include <cuda_runtime.h>
#include <cuda_bf16.h>
#include <cuda_fp16.h>
#include <cstdint>

#define N_NODES 50000
#define N_EDGES 800000
#define F_IN 128
#define HIDDEN 128
#define N_CLASSES 10
#define N_GRAPHS 256
#define SCAN_BLOCKS 196  // ceil(50000/256)
#define SPLIT 25024      // node-half boundary (multiple of 64)

#define TW 68  // words (bf16x2) per row in smem tiles: 64 data + 4 pad

// -------- scratch (static device globals; zero-initialized at load) --------
__device__ int g_degi[N_NODES];          // zeroed by scan1 after read
__device__ int g_off[N_NODES + 1];
__device__ int g_cur[N_NODES];
__device__ int g_bsum[256];
__device__ int g_csr_src[N_EDGES];
__device__ float g_gcnt[N_GRAPHS];       // zeroed by final_out after read
__device__ float g_pool[N_GRAPHS * N_CLASSES];  // zeroed by final_out after read
__device__ __align__(16) __half g_Ah[N_NODES * HIDDEN];  // fp16 message matrix
__device__ __align__(16) __half g_Bh[N_NODES * HIDDEN];  // fp16 self-term
__device__ __align__(16) __half g_Hh[N_NODES * HIDDEN];  // fp16 hidden
__device__ __align__(8) __half g_A3h[N_NODES * N_CLASSES];  // fp16, 5 uint/row
__device__ __align__(8) __half g_B3h[N_NODES * N_CLASSES];  // fp16, 5 uint/row

// -------- counts (accumulators start zero each call by invariant) --------
__global__ void count_kernel(const int* __restrict__ ei, const int* __restrict__ batch) {
    int e = blockIdx.x * blockDim.x + threadIdx.x;
    if (e < N_EDGES) atomicAdd(&g_degi[ei[N_EDGES + e]], 1);
    if (e < N_NODES) atomicAdd(&g_gcnt[batch[e]], 1.0f);
}

// -------- scan phase 1: per-block local exclusive scan + block sums --------
__global__ __launch_bounds__(256) void scan1_kernel() {
    __shared__ int ws[8];
    const int t = threadIdx.x;
    const int lane = t & 31;
    const int warp = t >> 5;
    const int i = blockIdx.x * 256 + t;
    int v = (i < N_NODES) ? g_degi[i] : 0;
    if (i < N_NODES) g_degi[i] = 0;  // restore zero-invariant for next call
    int x = v;
#pragma unroll
    for (int off = 1; off < 32; off <<= 1) {
        int y = __shfl_up_sync(0xFFFFFFFFu, x, off);
        if (lane >= off) x += y;
    }
    if (lane == 31) ws[warp] = x;
    __syncthreads();
    if (warp == 0 && lane < 8) {
        int s = ws[lane];
#pragma unroll
        for (int off = 1; off < 8; off <<= 1) {
            int y = __shfl_up_sync(0xFFu, s, off);
            if (lane >= off) s += y;
        }
        ws[lane] = s;
    }
    __syncthreads();
    int incl = x + (warp > 0 ? ws[warp - 1] : 0);
    if (i < N_NODES) g_off[i] = incl - v;
    if (t == 255) g_bsum[blockIdx.x] = incl;
}

// -------- scan phase 2+3 fused: each block reduces bsum[0..blockIdx) --------
__global__ __launch_bounds__(256) void scan23_kernel() {
    __shared__ int ws[8];
    const int t = threadIdx.x;
    const int lane = t & 31;
    const int warp = t >> 5;
    int v = (t < blockIdx.x && t < SCAN_BLOCKS) ? g_bsum[t] : 0;
#pragma unroll
    for (int off = 16; off > 0; off >>= 1) v += __shfl_xor_sync(0xFFFFFFFFu, v, off);
    if (lane == 0) ws[warp] = v;
    __syncthreads();
    int blockOff;
    {
        int s = ws[lane & 7];
#pragma unroll
        for (int off = 4; off > 0; off >>= 1) s += __shfl_xor_sync(0xFFFFFFFFu, s, off, 8);
        blockOff = s;
    }
    int i = blockIdx.x * 256 + t;
    if (i < N_NODES) {
        int o = g_off[i] + blockOff;
        g_off[i] = o;
        g_cur[i] = o;
    }
    if (i == 0) g_off[N_NODES] = N_EDGES;
}

__global__ void fill_csr_kernel(const int* __restrict__ ei) {
    int e = blockIdx.x * blockDim.x + threadIdx.x;
    if (e >= N_EDGES) return;
    int src = ei[e];
    int dst = ei[N_EDGES + e];
    int slot = atomicAdd(&g_cur[dst], 1);
    g_csr_src[slot] = src;
}

// ======== bf16 mma.sync dual GEMM (3-term compensated) ========
__device__ __forceinline__ uint32_t pack_hi(float a, float b) {
    __nv_bfloat162 h = __floats2bfloat162_rn(a, b);
    return *(uint32_t*)&h;
}
__device__ __forceinline__ uint32_t pack_lo(float a, float b, uint32_t hi) {
    __nv_bfloat162 h = *(__nv_bfloat162*)&hi;
    __nv_bfloat162 l =
        __floats2bfloat162_rn(a - __bfloat162float(h.x), b - __bfloat162float(h.y));
    return *(uint32_t*)&l;
}
__device__ __forceinline__ void mma_bf16(float* d, const uint32_t* a, uint32_t b0,
                                         uint32_t b1) {
    asm volatile(
        "mma.sync.aligned.m16n8k16.row.col.f32.bf16.bf16.f32 "
        "{%0,%1,%2,%3}, {%4,%5,%6,%7}, {%8,%9}, {%0,%1,%2,%3};"
        : "+f"(d[0]), "+f"(d[1]), "+f"(d[2]), "+f"(d[3])
        : "r"(a[0]), "r"(a[1]), "r"(a[2]), "r"(a[3]), "r"(b0), "r"(b1));
}

// One CTA: 64 rows, K=128; phase0: Wl -> Ah, phase1: Wr -> Bh (both fp16 out).
// 104.4KB smem -> 2 CTAs/SM. rowBase selects node half.
template <bool FP16IN>
__global__ __launch_bounds__(256, 2) void gemm_dual128_bf16(
    const void* __restrict__ Xv, const float* __restrict__ Wl,
    const float* __restrict__ Wr, __half* __restrict__ Ah, __half* __restrict__ Bh,
    int rowBase) {
    extern __shared__ uint32_t smw[];
    uint32_t* Xhi = smw;                  // [64][TW]
    uint32_t* Xlo = smw + 64 * TW;        // [64][TW]
    uint32_t* Wh = smw + 2 * 64 * TW;     // [128][TW]
    uint32_t* Wo = Wh + 128 * TW;         // [128][TW]
    const int tid = threadIdx.x;
    const int row0 = rowBase + blockIdx.x * 64;

    // ---- stage X (64 rows) -> Xhi/Xlo ----
    for (int i = tid; i < 64 * 32; i += 256) {
        int r = i >> 5, c4 = i & 31;
        int gr = row0 + r;
        float4 v;
        if (FP16IN) {
            uint2 u = (gr < N_NODES) ? ((const uint2*)Xv)[gr * 32 + c4]
                                     : make_uint2(0u, 0u);
            float2 p0 = __half22float2(*(__half2*)&u.x);
            float2 p1 = __half22float2(*(__half2*)&u.y);
            v = make_float4(p0.x, p0.y, p1.x, p1.y);
        } else {
            v = (gr < N_NODES) ? ((const float4*)Xv)[gr * 32 + c4]
                               : make_float4(0.f, 0.f, 0.f, 0.f);
        }
        uint32_t h0 = pack_hi(v.x, v.y), h1 = pack_hi(v.z, v.w);
        Xhi[r * TW + 2 * c4] = h0;
        Xhi[r * TW + 2 * c4 + 1] = h1;
        Xlo[r * TW + 2 * c4] = pack_lo(v.x, v.y, h0);
        Xlo[r * TW + 2 * c4 + 1] = pack_lo(v.z, v.w, h1);
    }

    const int warp = tid >> 5, lane = tid & 31;
    const int rb = (warp >> 1) * 16;  // 4 row-groups of 16
    const int nw = warp & 1;          // 2 col-groups of 64
    const int g = lane >> 2, tg = lane & 3;

    for (int phase = 0; phase < 2; phase++) {
        const float* W = phase ? Wr : Wl;
        __half* OUT = phase ? Bh : Ah;
        __syncthreads();  // Wh/Wo free (prev phase consumers done; X ready ph0)
        for (int i = tid; i < 128 * 64; i += 256) {
            int n = i & 127, j = i >> 7;  // j = k-pair index
            float w0 = W[(2 * j) * 128 + n], w1 = W[(2 * j + 1) * 128 + n];
            uint32_t h = pack_hi(w0, w1);
            Wh[n * TW + j] = h;
            Wo[n * TW + j] = pack_lo(w0, w1, h);
        }
        __syncthreads();

        float acc[8][4];
#pragma unroll
        for (int nt = 0; nt < 8; nt++)
#pragma unroll
            for (int q = 0; q < 4; q++) acc[nt][q] = 0.f;

#pragma unroll
        for (int ks = 0; ks < 8; ks++) {  // k16 steps
            const int j0 = ks * 8;
            uint32_t ahi[4], alo[4];
            ahi[0] = Xhi[(rb + g) * TW + j0 + tg];
            ahi[1] = Xhi[(rb + 8 + g) * TW + j0 + tg];
            ahi[2] = Xhi[(rb + g) * TW + j0 + 4 + tg];
            ahi[3] = Xhi[(rb + 8 + g) * TW + j0 + 4 + tg];
            alo[0] = Xlo[(rb + g) * TW + j0 + tg];
            alo[1] = Xlo[(rb + 8 + g) * TW + j0 + tg];
            alo[2] = Xlo[(rb + g) * TW + j0 + 4 + tg];
            alo[3] = Xlo[(rb + 8 + g) * TW + j0 + 4 + tg];
#pragma unroll
            for (int nt = 0; nt < 8; nt++) {
                int col = nw * 64 + nt * 8 + g;
                uint32_t bh0 = Wh[col * TW + j0 + tg];
                uint32_t bh1 = Wh[col * TW + j0 + 4 + tg];
                uint32_t bl0 = Wo[col * TW + j0 + tg];
                uint32_t bl1 = Wo[col * TW + j0 + 4 + tg];
                mma_bf16(acc[nt], ahi, bh0, bh1);
                mma_bf16(acc[nt], alo, bh0, bh1);
                mma_bf16(acc[nt], ahi, bl0, bl1);
            }
        }

        // epilogue -> fp16
        uint32_t* O32 = (uint32_t*)OUT;
        int gr0 = row0 + rb + g;
        int gr1 = gr0 + 8;
#pragma unroll
        for (int nt = 0; nt < 8; nt++) {
            int gc = nw * 64 + nt * 8 + tg * 2;
            if (gr0 < N_NODES) {
                __half2 p = __floats2half2_rn(acc[nt][0], acc[nt][1]);
                O32[gr0 * 64 + (gc >> 1)] = *(uint32_t*)&p;
            }
            if (gr1 < N_NODES) {
                __half2 p = __floats2half2_rn(acc[nt][2], acc[nt][3]);
                O32[gr1 * 64 + (gc >> 1)] = *(uint32_t*)&p;
            }
        }
    }
}

// -------- CSR gather + finalize: Hh = fp16(mean Ah[src] + Bh + bias) --------
__global__ __launch_bounds__(256) void gather_fin128(
    const __half* __restrict__ Ah, const __half* __restrict__ Bh,
    const float* __restrict__ bias, __half* __restrict__ Hh,
    int nodeBase, int nodeEnd) {
    int node = nodeBase + ((blockIdx.x * blockDim.x + threadIdx.x) >> 5);
    int lane = threadIdx.x & 31;
    if (node >= nodeEnd) return;
    const int beg = g_off[node];
    const int end = g_off[node + 1];
    const uint2* A2 = (const uint2*)Ah;  // 4 halves per uint2; 32 uint2 per row
    float4 acc = make_float4(0.f, 0.f, 0.f, 0.f);
    int j = beg;
    for (; j + 3 < end; j += 4) {
        int s0 = g_csr_src[j];
        int s1 = g_csr_src[j + 1];
        int s2 = g_csr_src[j + 2];
        int s3 = g_csr_src[j + 3];
        uint2 u0 = A2[s0 * 32 + lane];
        uint2 u1 = A2[s1 * 32 + lane];
        uint2 u2 = A2[s2 * 32 + lane];
        uint2 u3 = A2[s3 * 32 + lane];
        float2 a0 = __half22float2(*(__half2*)&u0.x), b0 = __half22float2(*(__half2*)&u0.y);
        float2 a1 = __half22float2(*(__half2*)&u1.x), b1 = __half22float2(*(__half2*)&u1.y);
        float2 a2 = __half22float2(*(__half2*)&u2.x), b2 = __half22float2(*(__half2*)&u2.y);
        float2 a3 = __half22float2(*(__half2*)&u3.x), b3 = __half22float2(*(__half2*)&u3.y);
        acc.x += (a0.x + a1.x) + (a2.x + a3.x);
        acc.y += (a0.y + a1.y) + (a2.y + a3.y);
        acc.z += (b0.x + b1.x) + (b2.x + b3.x);
        acc.w += (b0.y + b1.y) + (b2.y + b3.y);
    }
    for (; j < end; j++) {
        uint2 u = A2[g_csr_src[j] * 32 + lane];
        float2 a = __half22float2(*(__half2*)&u.x), b = __half22float2(*(__half2*)&u.y);
        acc.x += a.x; acc.y += a.y; acc.z += b.x; acc.w += b.y;
    }
    int deg = end - beg;
    float inv = 1.0f / (float)(deg > 1 ? deg : 1);
    uint2 ub = ((const uint2*)Bh)[node * 32 + lane];
    float2 bx = __half22float2(*(__half2*)&ub.x);
    float2 by = __half22float2(*(__half2*)&ub.y);
    float4 bi = ((const float4*)bias)[lane];
    __half2 h0 = __floats2half2_rn(acc.x * inv + bx.x + bi.x, acc.y * inv + bx.y + bi.y);
    __half2 h1 = __floats2half2_rn(acc.z * inv + by.x + bi.z, acc.w * inv + by.y + bi.w);
    uint2 o;
    o.x = *(uint32_t*)&h0;
    o.y = *(uint32_t*)&h1;
    ((uint2*)Hh)[node * 32 + lane] = o;
}

// -------- layer-3 dual GEMM: A3h = Hh@Wl3, B3h = Hh@Wr3 (fp16 out) --------
__global__ __launch_bounds__(256) void gemm_dual10(
    const __half* __restrict__ Hh, const float* __restrict__ Wl3,
    const float* __restrict__ Wr3, __half* __restrict__ A3h,
    __half* __restrict__ B3h, int base, int end) {
    __shared__ float sW[128 * 20];  // [k][0:10]=Wl3, [k][10:20]=Wr3
    const int tid = threadIdx.x;
    for (int i = tid; i < 128 * 10; i += 256) {
        int k = i / 10;
        int c = i - k * 10;
        sW[k * 20 + c] = Wl3[i];
        sW[k * 20 + 10 + c] = Wr3[i];
    }
    __syncthreads();
    int n = base + blockIdx.x * 256 + tid;
    if (n >= end) return;
    float accA[10], accB[10];
#pragma unroll
    for (int c = 0; c < 10; c++) { accA[c] = 0.f; accB[c] = 0.f; }
    const uint2* H2 = (const uint2*)Hh;
#pragma unroll 4
    for (int q = 0; q < 32; q++) {  // 32 uint2 = 128 halves
        uint2 u = H2[n * 32 + q];
        float2 p0 = __half22float2(*(__half2*)&u.x);
        float2 p1 = __half22float2(*(__half2*)&u.y);
        float hv[4] = {p0.x, p0.y, p1.x, p1.y};
#pragma unroll
        for (int j = 0; j < 4; j++) {
            const float* w = &sW[(q * 4 + j) * 20];
#pragma unroll
            for (int c = 0; c < 10; c++) {
                accA[c] += hv[j] * w[c];
                accB[c] += hv[j] * w[10 + c];
            }
        }
    }
    uint32_t* oa = (uint32_t*)A3h;
    uint32_t* ob = (uint32_t*)B3h;
#pragma unroll
    for (int c = 0; c < 5; c++) {
        __half2 pa = __floats2half2_rn(accA[2 * c], accA[2 * c + 1]);
        __half2 pb = __floats2half2_rn(accB[2 * c], accB[2 * c + 1]);
        oa[n * 5 + c] = *(uint32_t*)&pa;
        ob[n * 5 + c] = *(uint32_t*)&pb;
    }
}

// -------- layer-3 gather + finalize + graph pool (8 thr/node, 5 active) ------
__global__ __launch_bounds__(256) void gather10_pool(
    const __half* __restrict__ A3h, const __half* __restrict__ B3h,
    const float* __restrict__ bl3, const int* __restrict__ batch) {
    int gid = blockIdx.x * blockDim.x + threadIdx.x;
    int node = gid >> 3;
    int lane = gid & 7;
    if (node >= N_NODES || lane >= 5) return;
    const int beg = g_off[node];
    const int end = g_off[node + 1];
    const uint32_t* A3u = (const uint32_t*)A3h;
    float2 acc = make_float2(0.f, 0.f);
    for (int j = beg; j < end; j++) {
        uint32_t u = A3u[g_csr_src[j] * 5 + lane];
        float2 v = __half22float2(*(__half2*)&u);
        acc.x += v.x;
        acc.y += v.y;
    }
    int deg = end - beg;
    float inv = 1.0f / (float)(deg > 1 ? deg : 1);
    uint32_t ub = ((const uint32_t*)B3h)[node * 5 + lane];
    float2 b = __half22float2(*(__half2*)&ub);
    float h0 = acc.x * inv + b.x + bl3[2 * lane];
    float h1 = acc.y * inv + b.y + bl3[2 * lane + 1];
    float* p = &g_pool[batch[node] * N_CLASSES + 2 * lane];
    atomicAdd(p, h0);
    atomicAdd(p + 1, h1);
}

// -------- final: pooled mean + log_softmax; restore zero-invariant --------
__global__ void final_out_kernel(float* __restrict__ out) {
    int g = threadIdx.x;
    if (g >= N_GRAPHS) return;
    float cnt = g_gcnt[g];
    g_gcnt[g] = 0.f;
    float inv = 1.0f / (cnt > 1.0f ? cnt : 1.0f);
    float v[N_CLASSES];
    float mx = -1e30f;
#pragma unroll
    for (int c = 0; c < N_CLASSES; c++) {
        v[c] = g_pool[g * N_CLASSES + c] * inv;
        g_pool[g * N_CLASSES + c] = 0.f;
        mx = v[c] > mx ? v[c] : mx;
    }
    float s = 0.f;
#pragma unroll
    for (int c = 0; c < N_CLASSES; c++) s += expf(v[c] - mx);
    float ls = logf(s);
#pragma unroll
    for (int c = 0; c < N_CLASSES; c++) out[g * N_CLASSES + c] = v[c] - mx - ls;
}

// -------- host launch --------
extern "C" void kernel_launch(void* const* d_in, const int* in_sizes, int n_in,
                              void* d_out, int out_size) {
    const float* x = (const float*)d_in[0];
    const int* ei = (const int*)d_in[1];
    const int* batch = (const int*)d_in[2];
    const float* Wl1 = (const float*)d_in[3];
    const float* bl1 = (const float*)d_in[4];
    const float* Wr1 = (const float*)d_in[5];
    const float* Wl2 = (const float*)d_in[6];
    const float* bl2 = (const float*)d_in[7];
    const float* Wr2 = (const float*)d_in[8];
    const float* Wl3 = (const float*)d_in[9];
    const float* bl3 = (const float*)d_in[10];
    const float* Wr3 = (const float*)d_in[11];
    float* out = (float*)d_out;

    __half *Ah, *Bh, *Hh, *A3h, *B3h;
    cudaGetSymbolAddress((void**)&Ah, g_Ah);
    cudaGetSymbolAddress((void**)&Bh, g_Bh);
    cudaGetSymbolAddress((void**)&Hh, g_Hh);
    cudaGetSymbolAddress((void**)&A3h, g_A3h);
    cudaGetSymbolAddress((void**)&B3h, g_B3h);

    const int SMEM_BF = (2 * 64 * TW + 2 * 128 * TW) * 4;  // 104448 B
    cudaFuncSetAttribute(gemm_dual128_bf16<false>,
                         cudaFuncAttributeMaxDynamicSharedMemorySize, SMEM_BF);
    cudaFuncSetAttribute(gemm_dual128_bf16<true>,
                         cudaFuncAttributeMaxDynamicSharedMemorySize, SMEM_BF);

    // one-time side stream + events (created on the un-captured correctness call)
    static cudaStream_t s1 = nullptr;
    static cudaEvent_t evFork = nullptr, evCSR = nullptr, evGemm1 = nullptr,
                       evGa1 = nullptr, evGemm2 = nullptr, evGa2 = nullptr;
    if (s1 == nullptr) {
        cudaStreamCreateWithFlags(&s1, cudaStreamNonBlocking);
        cudaEventCreateWithFlags(&evFork, cudaEventDisableTiming);
        cudaEventCreateWithFlags(&evCSR, cudaEventDisableTiming);
        cudaEventCreateWithFlags(&evGemm1, cudaEventDisableTiming);
        cudaEventCreateWithFlags(&evGa1, cudaEventDisableTiming);
        cudaEventCreateWithFlags(&evGemm2, cudaEventDisableTiming);
        cudaEventCreateWithFlags(&evGa2, cudaEventDisableTiming);
    }

    const int H0 = SPLIT, H1 = N_NODES - SPLIT;           // 25024 / 24976
    const int gemm_grid_h = (H0 + 63) / 64;               // 391 (covers both halves)
    const int gath_grid_h0 = H0 / 8;                      // warp per node
    const int gath_grid_h1 = (H1 * 32 + 255) / 256;
    const int g10_grid = (H0 + 255) / 256;                // 98 (covers both halves)

    // ---- fork: compact-CSR build chain on side stream ----
    cudaEventRecord(evFork, 0);
    cudaStreamWaitEvent(s1, evFork, 0);
    count_kernel<<<(N_EDGES + 255) / 256, 256, 0, s1>>>(ei, batch);
    scan1_kernel<<<SCAN_BLOCKS, 256, 0, s1>>>();
    scan23_kernel<<<SCAN_BLOCKS, 256, 0, s1>>>();
    fill_csr_kernel<<<(N_EDGES + 255) / 256, 256, 0, s1>>>(ei);
    cudaEventRecord(evCSR, s1);

    // ---- layer-1 GEMM (both halves) on main, concurrent with CSR build ----
    gemm_dual128_bf16<false><<<gemm_grid_h, 256, SMEM_BF>>>(x, Wl1, Wr1, Ah, Bh, 0);
    gemm_dual128_bf16<false><<<gemm_grid_h, 256, SMEM_BF>>>(x, Wl1, Wr1, Ah, Bh, SPLIT);
    cudaEventRecord(evGemm1, 0);

    // ---- gather1: half0 on main, half1 on s1 ----
    cudaStreamWaitEvent(0, evCSR, 0);
    gather_fin128<<<gath_grid_h0, 256>>>(Ah, Bh, bl1, Hh, 0, SPLIT);
    cudaStreamWaitEvent(s1, evGemm1, 0);  // s1 has CSR in-stream already
    gather_fin128<<<gath_grid_h1, 256, 0, s1>>>(Ah, Bh, bl1, Hh, SPLIT, N_NODES);
    cudaEventRecord(evGa1, s1);

    // ---- layer-2 GEMM: half0 immediately (reads Hh[0:SPLIT] only) ----
    gemm_dual128_bf16<true><<<gemm_grid_h, 256, SMEM_BF>>>(Hh, Wl2, Wr2, Ah, Bh, 0);
    cudaStreamWaitEvent(0, evGa1, 0);
    gemm_dual128_bf16<true><<<gemm_grid_h, 256, SMEM_BF>>>(Hh, Wl2, Wr2, Ah, Bh, SPLIT);
    cudaEventRecord(evGemm2, 0);

    // ---- gather2: half0 on main, half1 on s1 ----
    gather_fin128<<<gath_grid_h0, 256>>>(Ah, Bh, bl2, Hh, 0, SPLIT);
    cudaStreamWaitEvent(s1, evGemm2, 0);
    gather_fin128<<<gath_grid_h1, 256, 0, s1>>>(Ah, Bh, bl2, Hh, SPLIT, N_NODES);
    cudaEventRecord(evGa2, s1);

    // ---- layer-3 GEMM: half0 overlaps s1's gather2_half1 ----
    gemm_dual10<<<g10_grid, 256>>>(Hh, Wl3, Wr3, A3h, B3h, 0, SPLIT);
    cudaStreamWaitEvent(0, evGa2, 0);
    gemm_dual10<<<g10_grid, 256>>>(Hh, Wl3, Wr3, A3h, B3h, SPLIT, N_NODES);

    // ---- layer-3 gather + pool + final ----
    gather10_pool<<<(N_NODES * 8 + 255) / 256, 256>>>(A3h, B3h, bl3, batch);
    final_out_kernel<<<1, 256>>>(out);
}

// round 15
// speedup vs baseline: 1.1822x; 1.1822x over previous
#include <cuda_runtime.h>
#include <cuda_bf16.h>
#include <cuda_fp16.h>
#include <cstdint>

#define N_NODES 50000
#define N_EDGES 800000
#define F_IN 128
#define HIDDEN 128
#define N_CLASSES 10
#define N_GRAPHS 256
#define SCAN_BLOCKS 196  // ceil(50000/256)
#define EHALF 400000     // edge-range split for the two concurrent fill halves

#define TW 68  // words (bf16x2) per row in smem tiles: 64 data + 4 pad

// -------- scratch (static device globals; zero-initialized at load) --------
__device__ int g_degi[N_NODES];          // zeroed by scan1 after read
__device__ int g_off[N_NODES + 1];
__device__ int g_cur[N_NODES];
__device__ int g_bsum[256];
__device__ int g_csr_src[N_EDGES];
__device__ float g_gcnt[N_GRAPHS];       // zeroed by final_out after read
__device__ float g_pool[N_GRAPHS * N_CLASSES];  // zeroed by final_out after read
__device__ __align__(16) __half g_Ah[N_NODES * HIDDEN];  // fp16 message matrix
__device__ __align__(16) __half g_Bh[N_NODES * HIDDEN];  // fp16 self-term
__device__ __align__(16) __half g_Hh[N_NODES * HIDDEN];  // fp16 hidden
__device__ __align__(8) __half g_A3h[N_NODES * N_CLASSES];  // fp16, 5 uint/row
__device__ __align__(8) __half g_B3h[N_NODES * N_CLASSES];  // fp16, 5 uint/row

// -------- counts: 2 edges / 2 nodes per thread (int2 loads) --------
__global__ void count_kernel(const int* __restrict__ ei, const int* __restrict__ batch) {
    int t = blockIdx.x * blockDim.x + threadIdx.x;
    if (t < N_EDGES / 2) {
        int2 d = ((const int2*)(ei + N_EDGES))[t];
        atomicAdd(&g_degi[d.x], 1);
        atomicAdd(&g_degi[d.y], 1);
    }
    if (t < N_NODES / 2) {
        int2 b = ((const int2*)batch)[t];
        atomicAdd(&g_gcnt[b.x], 1.0f);
        atomicAdd(&g_gcnt[b.y], 1.0f);
    }
}

// -------- scan phase 1: per-block local exclusive scan + block sums --------
__global__ __launch_bounds__(256) void scan1_kernel() {
    __shared__ int ws[8];
    const int t = threadIdx.x;
    const int lane = t & 31;
    const int warp = t >> 5;
    const int i = blockIdx.x * 256 + t;
    int v = (i < N_NODES) ? g_degi[i] : 0;
    if (i < N_NODES) g_degi[i] = 0;  // restore zero-invariant for next call
    int x = v;
#pragma unroll
    for (int off = 1; off < 32; off <<= 1) {
        int y = __shfl_up_sync(0xFFFFFFFFu, x, off);
        if (lane >= off) x += y;
    }
    if (lane == 31) ws[warp] = x;
    __syncthreads();
    if (warp == 0 && lane < 8) {
        int s = ws[lane];
#pragma unroll
        for (int off = 1; off < 8; off <<= 1) {
            int y = __shfl_up_sync(0xFFu, s, off);
            if (lane >= off) s += y;
        }
        ws[lane] = s;
    }
    __syncthreads();
    int incl = x + (warp > 0 ? ws[warp - 1] : 0);
    if (i < N_NODES) g_off[i] = incl - v;
    if (t == 255) g_bsum[blockIdx.x] = incl;
}

// -------- scan phase 2+3 fused: each block reduces bsum[0..blockIdx) --------
__global__ __launch_bounds__(256) void scan23_kernel() {
    __shared__ int ws[8];
    const int t = threadIdx.x;
    const int lane = t & 31;
    const int warp = t >> 5;
    int v = (t < blockIdx.x && t < SCAN_BLOCKS) ? g_bsum[t] : 0;
#pragma unroll
    for (int off = 16; off > 0; off >>= 1) v += __shfl_xor_sync(0xFFFFFFFFu, v, off);
    if (lane == 0) ws[warp] = v;
    __syncthreads();
    int blockOff;
    {
        int s = ws[lane & 7];
#pragma unroll
        for (int off = 4; off > 0; off >>= 1) s += __shfl_xor_sync(0xFFFFFFFFu, s, off, 8);
        blockOff = s;
    }
    int i = blockIdx.x * 256 + t;
    if (i < N_NODES) {
        int o = g_off[i] + blockOff;
        g_off[i] = o;
        g_cur[i] = o;
    }
    if (i == 0) g_off[N_NODES] = N_EDGES;
}

// -------- CSR fill over an edge range (run as two concurrent halves) --------
__global__ void fill_csr_kernel(const int* __restrict__ ei, int eBeg, int eEnd) {
    int e = eBeg + blockIdx.x * blockDim.x + threadIdx.x;
    if (e >= eEnd) return;
    int src = ei[e];
    int dst = ei[N_EDGES + e];
    int slot = atomicAdd(&g_cur[dst], 1);
    g_csr_src[slot] = src;
}

// ======== bf16 mma.sync dual GEMM (3-term compensated) ========
__device__ __forceinline__ uint32_t pack_hi(float a, float b) {
    __nv_bfloat162 h = __floats2bfloat162_rn(a, b);
    return *(uint32_t*)&h;
}
__device__ __forceinline__ uint32_t pack_lo(float a, float b, uint32_t hi) {
    __nv_bfloat162 h = *(__nv_bfloat162*)&hi;
    __nv_bfloat162 l =
        __floats2bfloat162_rn(a - __bfloat162float(h.x), b - __bfloat162float(h.y));
    return *(uint32_t*)&l;
}
__device__ __forceinline__ void mma_bf16(float* d, const uint32_t* a, uint32_t b0,
                                         uint32_t b1) {
    asm volatile(
        "mma.sync.aligned.m16n8k16.row.col.f32.bf16.bf16.f32 "
        "{%0,%1,%2,%3}, {%4,%5,%6,%7}, {%8,%9}, {%0,%1,%2,%3};"
        : "+f"(d[0]), "+f"(d[1]), "+f"(d[2]), "+f"(d[3])
        : "r"(a[0]), "r"(a[1]), "r"(a[2]), "r"(a[3]), "r"(b0), "r"(b1));
}

// One CTA: 64 rows, K=128; phase0: Wl -> Ah, phase1: Wr -> Bh (both fp16 out).
// 104.4KB smem -> 2 CTAs/SM. W staged per phase.
template <bool FP16IN>
__global__ __launch_bounds__(256, 2) void gemm_dual128_bf16(
    const void* __restrict__ Xv, const float* __restrict__ Wl,
    const float* __restrict__ Wr, __half* __restrict__ Ah, __half* __restrict__ Bh) {
    extern __shared__ uint32_t smw[];
    uint32_t* Xhi = smw;                  // [64][TW]
    uint32_t* Xlo = smw + 64 * TW;        // [64][TW]
    uint32_t* Wh = smw + 2 * 64 * TW;     // [128][TW]
    uint32_t* Wo = Wh + 128 * TW;         // [128][TW]
    const int tid = threadIdx.x;
    const int row0 = blockIdx.x * 64;

    // ---- stage X (64 rows) -> Xhi/Xlo ----
    for (int i = tid; i < 64 * 32; i += 256) {
        int r = i >> 5, c4 = i & 31;
        int gr = row0 + r;
        float4 v;
        if (FP16IN) {
            uint2 u = (gr < N_NODES) ? ((const uint2*)Xv)[gr * 32 + c4]
                                     : make_uint2(0u, 0u);
            float2 p0 = __half22float2(*(__half2*)&u.x);
            float2 p1 = __half22float2(*(__half2*)&u.y);
            v = make_float4(p0.x, p0.y, p1.x, p1.y);
        } else {
            v = (gr < N_NODES) ? ((const float4*)Xv)[gr * 32 + c4]
                               : make_float4(0.f, 0.f, 0.f, 0.f);
        }
        uint32_t h0 = pack_hi(v.x, v.y), h1 = pack_hi(v.z, v.w);
        Xhi[r * TW + 2 * c4] = h0;
        Xhi[r * TW + 2 * c4 + 1] = h1;
        Xlo[r * TW + 2 * c4] = pack_lo(v.x, v.y, h0);
        Xlo[r * TW + 2 * c4 + 1] = pack_lo(v.z, v.w, h1);
    }

    const int warp = tid >> 5, lane = tid & 31;
    const int rb = (warp >> 1) * 16;  // 4 row-groups of 16
    const int nw = warp & 1;          // 2 col-groups of 64
    const int g = lane >> 2, tg = lane & 3;

    for (int phase = 0; phase < 2; phase++) {
        const float* W = phase ? Wr : Wl;
        __half* OUT = phase ? Bh : Ah;
        __syncthreads();  // Wh/Wo free (prev phase consumers done; X ready ph0)
        for (int i = tid; i < 128 * 64; i += 256) {
            int n = i & 127, j = i >> 7;  // j = k-pair index
            float w0 = W[(2 * j) * 128 + n], w1 = W[(2 * j + 1) * 128 + n];
            uint32_t h = pack_hi(w0, w1);
            Wh[n * TW + j] = h;
            Wo[n * TW + j] = pack_lo(w0, w1, h);
        }
        __syncthreads();

        float acc[8][4];
#pragma unroll
        for (int nt = 0; nt < 8; nt++)
#pragma unroll
            for (int q = 0; q < 4; q++) acc[nt][q] = 0.f;

#pragma unroll
        for (int ks = 0; ks < 8; ks++) {  // k16 steps
            const int j0 = ks * 8;
            uint32_t ahi[4], alo[4];
            ahi[0] = Xhi[(rb + g) * TW + j0 + tg];
            ahi[1] = Xhi[(rb + 8 + g) * TW + j0 + tg];
            ahi[2] = Xhi[(rb + g) * TW + j0 + 4 + tg];
            ahi[3] = Xhi[(rb + 8 + g) * TW + j0 + 4 + tg];
            alo[0] = Xlo[(rb + g) * TW + j0 + tg];
            alo[1] = Xlo[(rb + 8 + g) * TW + j0 + tg];
            alo[2] = Xlo[(rb + g) * TW + j0 + 4 + tg];
            alo[3] = Xlo[(rb + 8 + g) * TW + j0 + 4 + tg];
#pragma unroll
            for (int nt = 0; nt < 8; nt++) {
                int col = nw * 64 + nt * 8 + g;
                uint32_t bh0 = Wh[col * TW + j0 + tg];
                uint32_t bh1 = Wh[col * TW + j0 + 4 + tg];
                uint32_t bl0 = Wo[col * TW + j0 + tg];
                uint32_t bl1 = Wo[col * TW + j0 + 4 + tg];
                mma_bf16(acc[nt], ahi, bh0, bh1);
                mma_bf16(acc[nt], alo, bh0, bh1);
                mma_bf16(acc[nt], ahi, bl0, bl1);
            }
        }

        // epilogue -> fp16
        uint32_t* O32 = (uint32_t*)OUT;
        int gr0 = row0 + rb + g;
        int gr1 = gr0 + 8;
#pragma unroll
        for (int nt = 0; nt < 8; nt++) {
            int gc = nw * 64 + nt * 8 + tg * 2;
            if (gr0 < N_NODES) {
                __half2 p = __floats2half2_rn(acc[nt][0], acc[nt][1]);
                O32[gr0 * 64 + (gc >> 1)] = *(uint32_t*)&p;
            }
            if (gr1 < N_NODES) {
                __half2 p = __floats2half2_rn(acc[nt][2], acc[nt][3]);
                O32[gr1 * 64 + (gc >> 1)] = *(uint32_t*)&p;
            }
        }
    }
}

// -------- CSR gather + finalize: Hh = fp16(mean Ah[src] + Bh + bias) --------
__global__ __launch_bounds__(256) void gather_fin128(
    const __half* __restrict__ Ah, const __half* __restrict__ Bh,
    const float* __restrict__ bias, __half* __restrict__ Hh) {
    int node = (blockIdx.x * blockDim.x + threadIdx.x) >> 5;
    int lane = threadIdx.x & 31;
    if (node >= N_NODES) return;
    const int beg = g_off[node];
    const int end = g_off[node + 1];
    const uint2* A2 = (const uint2*)Ah;  // 4 halves per uint2; 32 uint2 per row
    float4 acc = make_float4(0.f, 0.f, 0.f, 0.f);
    int j = beg;
    for (; j + 3 < end; j += 4) {
        int s0 = g_csr_src[j];
        int s1 = g_csr_src[j + 1];
        int s2 = g_csr_src[j + 2];
        int s3 = g_csr_src[j + 3];
        uint2 u0 = A2[s0 * 32 + lane];
        uint2 u1 = A2[s1 * 32 + lane];
        uint2 u2 = A2[s2 * 32 + lane];
        uint2 u3 = A2[s3 * 32 + lane];
        float2 a0 = __half22float2(*(__half2*)&u0.x), b0 = __half22float2(*(__half2*)&u0.y);
        float2 a1 = __half22float2(*(__half2*)&u1.x), b1 = __half22float2(*(__half2*)&u1.y);
        float2 a2 = __half22float2(*(__half2*)&u2.x), b2 = __half22float2(*(__half2*)&u2.y);
        float2 a3 = __half22float2(*(__half2*)&u3.x), b3 = __half22float2(*(__half2*)&u3.y);
        acc.x += (a0.x + a1.x) + (a2.x + a3.x);
        acc.y += (a0.y + a1.y) + (a2.y + a3.y);
        acc.z += (b0.x + b1.x) + (b2.x + b3.x);
        acc.w += (b0.y + b1.y) + (b2.y + b3.y);
    }
    for (; j < end; j++) {
        uint2 u = A2[g_csr_src[j] * 32 + lane];
        float2 a = __half22float2(*(__half2*)&u.x), b = __half22float2(*(__half2*)&u.y);
        acc.x += a.x; acc.y += a.y; acc.z += b.x; acc.w += b.y;
    }
    int deg = end - beg;
    float inv = 1.0f / (float)(deg > 1 ? deg : 1);
    uint2 ub = ((const uint2*)Bh)[node * 32 + lane];
    float2 bx = __half22float2(*(__half2*)&ub.x);
    float2 by = __half22float2(*(__half2*)&ub.y);
    float4 bi = ((const float4*)bias)[lane];
    __half2 h0 = __floats2half2_rn(acc.x * inv + bx.x + bi.x, acc.y * inv + bx.y + bi.y);
    __half2 h1 = __floats2half2_rn(acc.z * inv + by.x + bi.z, acc.w * inv + by.y + bi.w);
    uint2 o;
    o.x = *(uint32_t*)&h0;
    o.y = *(uint32_t*)&h1;
    ((uint2*)Hh)[node * 32 + lane] = o;
}

// -------- layer-3 dual GEMM: A3h = Hh@Wl3, B3h = Hh@Wr3 (fp16 out) --------
__global__ __launch_bounds__(256) void gemm_dual10(
    const __half* __restrict__ Hh, const float* __restrict__ Wl3,
    const float* __restrict__ Wr3, __half* __restrict__ A3h,
    __half* __restrict__ B3h) {
    __shared__ float sW[128 * 20];  // [k][0:10]=Wl3, [k][10:20]=Wr3
    const int tid = threadIdx.x;
    for (int i = tid; i < 128 * 10; i += 256) {
        int k = i / 10;
        int c = i - k * 10;
        sW[k * 20 + c] = Wl3[i];
        sW[k * 20 + 10 + c] = Wr3[i];
    }
    __syncthreads();
    int n = blockIdx.x * 256 + tid;
    if (n >= N_NODES) return;
    float accA[10], accB[10];
#pragma unroll
    for (int c = 0; c < 10; c++) { accA[c] = 0.f; accB[c] = 0.f; }
    const uint2* H2 = (const uint2*)Hh;
#pragma unroll 4
    for (int q = 0; q < 32; q++) {  // 32 uint2 = 128 halves
        uint2 u = H2[n * 32 + q];
        float2 p0 = __half22float2(*(__half2*)&u.x);
        float2 p1 = __half22float2(*(__half2*)&u.y);
        float hv[4] = {p0.x, p0.y, p1.x, p1.y};
#pragma unroll
        for (int j = 0; j < 4; j++) {
            const float* w = &sW[(q * 4 + j) * 20];
#pragma unroll
            for (int c = 0; c < 10; c++) {
                accA[c] += hv[j] * w[c];
                accB[c] += hv[j] * w[10 + c];
            }
        }
    }
    uint32_t* oa = (uint32_t*)A3h;
    uint32_t* ob = (uint32_t*)B3h;
#pragma unroll
    for (int c = 0; c < 5; c++) {
        __half2 pa = __floats2half2_rn(accA[2 * c], accA[2 * c + 1]);
        __half2 pb = __floats2half2_rn(accB[2 * c], accB[2 * c + 1]);
        oa[n * 5 + c] = *(uint32_t*)&pa;
        ob[n * 5 + c] = *(uint32_t*)&pb;
    }
}

// -------- layer-3 gather + finalize + graph pool (8 thr/node, 5 active) ------
__global__ __launch_bounds__(256) void gather10_pool(
    const __half* __restrict__ A3h, const __half* __restrict__ B3h,
    const float* __restrict__ bl3, const int* __restrict__ batch) {
    int gid = blockIdx.x * blockDim.x + threadIdx.x;
    int node = gid >> 3;
    int lane = gid & 7;
    if (node >= N_NODES || lane >= 5) return;
    const int beg = g_off[node];
    const int end = g_off[node + 1];
    const uint32_t* A3u = (const uint32_t*)A3h;
    float2 acc = make_float2(0.f, 0.f);
    for (int j = beg; j < end; j++) {
        uint32_t u = A3u[g_csr_src[j] * 5 + lane];
        float2 v = __half22float2(*(__half2*)&u);
        acc.x += v.x;
        acc.y += v.y;
    }
    int deg = end - beg;
    float inv = 1.0f / (float)(deg > 1 ? deg : 1);
    uint32_t ub = ((const uint32_t*)B3h)[node * 5 + lane];
    float2 b = __half22float2(*(__half2*)&ub);
    float h0 = acc.x * inv + b.x + bl3[2 * lane];
    float h1 = acc.y * inv + b.y + bl3[2 * lane + 1];
    float* p = &g_pool[batch[node] * N_CLASSES + 2 * lane];
    atomicAdd(p, h0);
    atomicAdd(p + 1, h1);
}

// -------- final: pooled mean + log_softmax; restore zero-invariant --------
__global__ void final_out_kernel(float* __restrict__ out) {
    int g = threadIdx.x;
    if (g >= N_GRAPHS) return;
    float cnt = g_gcnt[g];
    g_gcnt[g] = 0.f;
    float inv = 1.0f / (cnt > 1.0f ? cnt : 1.0f);
    float v[N_CLASSES];
    float mx = -1e30f;
#pragma unroll
    for (int c = 0; c < N_CLASSES; c++) {
        v[c] = g_pool[g * N_CLASSES + c] * inv;
        g_pool[g * N_CLASSES + c] = 0.f;
        mx = v[c] > mx ? v[c] : mx;
    }
    float s = 0.f;
#pragma unroll
    for (int c = 0; c < N_CLASSES; c++) s += expf(v[c] - mx);
    float ls = logf(s);
#pragma unroll
    for (int c = 0; c < N_CLASSES; c++) out[g * N_CLASSES + c] = v[c] - mx - ls;
}

// -------- host launch --------
extern "C" void kernel_launch(void* const* d_in, const int* in_sizes, int n_in,
                              void* d_out, int out_size) {
    const float* x = (const float*)d_in[0];
    const int* ei = (const int*)d_in[1];
    const int* batch = (const int*)d_in[2];
    const float* Wl1 = (const float*)d_in[3];
    const float* bl1 = (const float*)d_in[4];
    const float* Wr1 = (const float*)d_in[5];
    const float* Wl2 = (const float*)d_in[6];
    const float* bl2 = (const float*)d_in[7];
    const float* Wr2 = (const float*)d_in[8];
    const float* Wl3 = (const float*)d_in[9];
    const float* bl3 = (const float*)d_in[10];
    const float* Wr3 = (const float*)d_in[11];
    float* out = (float*)d_out;

    __half *Ah, *Bh, *Hh, *A3h, *B3h;
    cudaGetSymbolAddress((void**)&Ah, g_Ah);
    cudaGetSymbolAddress((void**)&Bh, g_Bh);
    cudaGetSymbolAddress((void**)&Hh, g_Hh);
    cudaGetSymbolAddress((void**)&A3h, g_A3h);
    cudaGetSymbolAddress((void**)&B3h, g_B3h);

    const int SMEM_BF = (2 * 64 * TW + 2 * 128 * TW) * 4;  // 104448 B
    cudaFuncSetAttribute(gemm_dual128_bf16<false>,
                         cudaFuncAttributeMaxDynamicSharedMemorySize, SMEM_BF);
    cudaFuncSetAttribute(gemm_dual128_bf16<true>,
                         cudaFuncAttributeMaxDynamicSharedMemorySize, SMEM_BF);

    // one-time side stream + events (created on the un-captured correctness call)
    static cudaStream_t s1 = nullptr;
    static cudaEvent_t evFork = nullptr, evScan = nullptr, evFillLo = nullptr;
    if (s1 == nullptr) {
        cudaStreamCreateWithFlags(&s1, cudaStreamNonBlocking);
        cudaEventCreateWithFlags(&evFork, cudaEventDisableTiming);
        cudaEventCreateWithFlags(&evScan, cudaEventDisableTiming);
        cudaEventCreateWithFlags(&evFillLo, cudaEventDisableTiming);
    }

    const int gemm_grid = (N_NODES + 63) / 64;          // 782
    const int warp_grid = (N_NODES * 32 + 255) / 256;   // warp per node
    const int fill_grid = (EHALF + 255) / 256;          // per half

    // ---- fork: CSR chain head on side stream ----
    cudaEventRecord(evFork, 0);
    cudaStreamWaitEvent(s1, evFork, 0);
    count_kernel<<<(N_EDGES / 2 + 255) / 256, 256, 0, s1>>>(ei, batch);
    scan1_kernel<<<SCAN_BLOCKS, 256, 0, s1>>>();
    scan23_kernel<<<SCAN_BLOCKS, 256, 0, s1>>>();
    cudaEventRecord(evScan, s1);
    fill_csr_kernel<<<fill_grid, 256, 0, s1>>>(ei, 0, EHALF);  // low half on s1
    cudaEventRecord(evFillLo, s1);

    // ---- layer-1 GEMM (full) on main, concurrent with CSR head ----
    gemm_dual128_bf16<false><<<gemm_grid, 256, SMEM_BF>>>(x, Wl1, Wr1, Ah, Bh);

    // ---- main helps fill the high half, then joins ----
    cudaStreamWaitEvent(0, evScan, 0);
    fill_csr_kernel<<<fill_grid, 256>>>(ei, EHALF, N_EDGES);  // high half on main
    cudaStreamWaitEvent(0, evFillLo, 0);

    // ---- layer 1 gather ----
    gather_fin128<<<warp_grid, 256>>>(Ah, Bh, bl1, Hh);

    // ---- layer 2 ----
    gemm_dual128_bf16<true><<<gemm_grid, 256, SMEM_BF>>>(Hh, Wl2, Wr2, Ah, Bh);
    gather_fin128<<<warp_grid, 256>>>(Ah, Bh, bl2, Hh);

    // ---- layer 3: both terms per node (fp16), then gather + pool ----
    gemm_dual10<<<(N_NODES + 255) / 256, 256>>>(Hh, Wl3, Wr3, A3h, B3h);
    gather10_pool<<<(N_NODES * 8 + 255) / 256, 256>>>(A3h, B3h, bl3, batch);

    final_out_kernel<<<1, 256>>>(out);
}